// round 10
// baseline (speedup 1.0000x reference)
#include <cuda_runtime.h>

// SSIM loss, fused single kernel, f32x2-packed separable 11x11 Gaussian conv.
// 4-channel reformulation: s=cx+cy, d=cx-cy; conv (s, d, s^2, d^2).
//   P=mu_s^2, Q=mu_d^2, A=E[s^2], B=E[d^2]:
//   num = ((P-Q)/2+C1) * ((A-B-P+Q)/2+C2)
//   den = ((P+Q)/2+C1) * ((A+B-P-Q)/2+C2)
// 32x32 tile + halo 5, static SMEM. Phase 2 uses 3-row groups (231 items,
// 8 busy warps) to balance warp issue. Epilogue: one MUFU.RCP per 4 px.

#define TW 32
#define TH 32
#define HALO 5
#define KS 11
#define HWD 42
#define HROWS 45          // padded ss/sd rows (3-row-group overrun)
#define TH_P 33           // padded sv2 rows (discarded row 32)
#define SWX 48            // ss/sd row stride (floats)
#define S2  22            // sv2 row stride (u64 elems)

typedef unsigned long long u64t;

__device__ double g_acc = 0.0;
__device__ unsigned int g_cnt = 0;

__device__ constexpr float GW[11] = {
    0.00102838f, 0.00759876f, 0.03600078f, 0.10936069f, 0.21300553f,
    0.26601173f,
    0.21300553f, 0.10936069f, 0.03600078f, 0.00759876f, 0.00102838f};

__device__ __forceinline__ u64t pk2(float lo, float hi) {
    u64t r; asm("mov.b64 %0,{%1,%2};" : "=l"(r) : "f"(lo), "f"(hi)); return r;
}
__device__ __forceinline__ void upk2(u64t v, float& lo, float& hi) {
    asm("mov.b64 {%0,%1},%2;" : "=f"(lo), "=f"(hi) : "l"(v));
}
__device__ __forceinline__ u64t fma2_(u64t a, u64t b, u64t c) {
    u64t d; asm("fma.rn.f32x2 %0,%1,%2,%3;" : "=l"(d) : "l"(a), "l"(b), "l"(c)); return d;
}
__device__ __forceinline__ u64t mul2_(u64t a, u64t b) {
    u64t d; asm("mul.rn.f32x2 %0,%1,%2;" : "=l"(d) : "l"(a), "l"(b)); return d;
}
__device__ __forceinline__ u64t add2_(u64t a, u64t b) {
    u64t d; asm("add.rn.f32x2 %0,%1,%2;" : "=l"(d) : "l"(a), "l"(b)); return d;
}
__device__ __forceinline__ u64t sub2_(u64t a, u64t b) {
    u64t d; asm("sub.rn.f32x2 %0,%1,%2;" : "=l"(d) : "l"(a), "l"(b)); return d;
}

__device__ __forceinline__ constexpr int WS(int j) { return j < 6 ? j : 10 - j; }

__global__ __launch_bounds__(256, 4)
void ssim_main_k(const float* __restrict__ A, const float* __restrict__ Bp,
                 float* __restrict__ out) {
    __shared__ __align__(16) float ss[HROWS][SWX];
    __shared__ __align__(16) float sd[HROWS][SWX];
    __shared__ __align__(16) u64t  sv2[4][TH_P][S2];
    __shared__ float red[8];

    const int tid = threadIdx.x;
    const int tx0 = blockIdx.x * TW;
    const int ty0 = blockIdx.y * TH;
    const size_t base = (size_t)blockIdx.z * (512 * 512);

    u64t wq[6];
#pragma unroll
    for (int j = 0; j < 6; j++) wq[j] = pk2(GW[j], GW[j]);

    // -------- Phase 1: halo load, clip, form s=cx+cy, d=cx-cy ---------------
    // rows 0..41 valid; row 42 is touched only by the discarded output row.
    // Zero it so no NaNs circulate.
    if (tid < HWD + HWD) {
        int c = tid - (tid >= HWD ? HWD : 0);
        float* dst = (tid >= HWD) ? &sd[42][0] : &ss[42][0];
        dst[c] = 0.f;
    }
    const bool interior = (blockIdx.x != 0) && (blockIdx.x != 15) &&
                          (blockIdx.y != 0) && (blockIdx.y != 15);
    if (interior) {
#pragma unroll
        for (int i = tid; i < HWD * HWD; i += 256) {
            int r = i / HWD, c = i - r * HWD;
            size_t idx = base + (size_t)(ty0 + r - HALO) * 512 + (tx0 + c - HALO);
            float cx = __saturatef(__ldg(A + idx));
            float cy = __saturatef(__ldg(Bp + idx));
            ss[r][c] = cx + cy;
            sd[r][c] = cx - cy;
        }
    } else {
#pragma unroll
        for (int i = tid; i < HWD * HWD; i += 256) {
            int r = i / HWD, c = i - r * HWD;
            int gy = ty0 + r - HALO, gx = tx0 + c - HALO;
            float cx = 0.f, cy = 0.f;
            if ((unsigned)gy < 512u && (unsigned)gx < 512u) {
                size_t idx = base + (size_t)gy * 512 + gx;
                cx = __saturatef(__ldg(A + idx));
                cy = __saturatef(__ldg(Bp + idx));
            }
            ss[r][c] = cx + cy;
            sd[r][c] = cx - cy;
        }
    }
    __syncthreads();

    // -------- Phase 2: vertical conv of (s, d, s^2, d^2), col-pair packed ----
    // 231 items = 11 rowgroups (3 rows each) x 21 packed col-pairs.
    // Rowgroup 10 produces rows 30,31,32; row 32 lands in sv2 padding and is
    // never read.
    if (tid < 231) {
        const int g = tid / 21;
        const int k = tid - 21 * g;
        const int r0 = g * 3;
        u64t as_[3] = {0,0,0}, ad_[3] = {0,0,0};
        u64t ass[3] = {0,0,0}, add_[3] = {0,0,0};
        const float* ps = &ss[r0][2 * k];
        const float* pd = &sd[r0][2 * k];
#pragma unroll
        for (int p = 0; p < 13; p++) {
            float2 sv = *(const float2*)(ps + p * SWX);
            float2 dv = *(const float2*)(pd + p * SWX);
            u64t S = pk2(sv.x, sv.y);
            u64t D = pk2(dv.x, dv.y);
            u64t SS = mul2_(S, S);
            u64t DD = mul2_(D, D);
#pragma unroll
            for (int o = 0; o < 3; o++) {
                int j = p - o;
                if (j >= 0 && j < KS) {
                    u64t w = wq[WS(j)];
                    as_[o]  = fma2_(w, S,  as_[o]);
                    ad_[o]  = fma2_(w, D,  ad_[o]);
                    ass[o]  = fma2_(w, SS, ass[o]);
                    add_[o] = fma2_(w, DD, add_[o]);
                }
            }
        }
#pragma unroll
        for (int o = 0; o < 3; o++) {
            int row = r0 + o;
            sv2[0][row][k] = as_[o];
            sv2[1][row][k] = ad_[o];
            sv2[2][row][k] = ass[o];
            sv2[3][row][k] = add_[o];
        }
    }
    __syncthreads();

    // -------- Phase 3: horizontal conv + SSIM, 256 items ---------------------
    // item = 1 row x 4 output cols (2 packed outputs); 32 rows x 8 colgroups
    float lsum = 0.f;
    {
        const int r  = tid >> 3;
        const int cg = tid & 7;
        const int m0 = 2 * cg;           // packed elems m0 .. m0+6
        u64t acc[4][2];
#pragma unroll
        for (int ch = 0; ch < 4; ch++) {
            const u64t* rowp = &sv2[ch][r][m0];
            u64t E[7];
            ulonglong2 q0 = *(const ulonglong2*)(rowp);
            ulonglong2 q1 = *(const ulonglong2*)(rowp + 2);
            ulonglong2 q2 = *(const ulonglong2*)(rowp + 4);
            E[0] = q0.x; E[1] = q0.y; E[2] = q1.x; E[3] = q1.y;
            E[4] = q2.x; E[5] = q2.y; E[6] = rowp[6];
            float flo[7], fhi[7];
#pragma unroll
            for (int t = 0; t < 7; t++) upk2(E[t], flo[t], fhi[t]);
            u64t O[6];
#pragma unroll
            for (int t = 0; t < 6; t++) O[t] = pk2(fhi[t], flo[t + 1]);
#pragma unroll
            for (int o = 0; o < 2; o++) {
                u64t a = mul2_(wq[WS(0)], E[o]);
#pragma unroll
                for (int j = 1; j < KS; j++) {
                    u64t v = (j & 1) ? O[o + (j - 1) / 2] : E[o + j / 2];
                    a = fma2_(wq[WS(j)], v, a);
                }
                acc[ch][o] = a;
            }
        }
        const u64t HALF = pk2(0.5f, 0.5f);
        const u64t C1q = pk2(1e-4f, 1e-4f);
        const u64t C2q = pk2(9e-4f, 9e-4f);
        float rr[2], qq[2];
#pragma unroll
        for (int o = 0; o < 2; o++) {
            u64t mus = acc[0][o], mud = acc[1][o];
            u64t Aq  = acc[2][o], Bq  = acc[3][o];
            u64t P = mul2_(mus, mus);
            u64t Q = mul2_(mud, mud);
            u64t PQd = sub2_(P, Q);
            u64t PQs = add2_(P, Q);
            u64t ABd = sub2_(Aq, Bq);
            u64t ABs = add2_(Aq, Bq);
            u64t nl = fma2_(HALF, PQd, C1q);              // (P-Q)/2 + C1
            u64t nr = fma2_(HALF, sub2_(ABd, PQd), C2q);  // (A-B-P+Q)/2 + C2
            u64t dl = fma2_(HALF, PQs, C1q);              // (P+Q)/2 + C1
            u64t dr = fma2_(HALF, sub2_(ABs, PQs), C2q);  // (A+B-P-Q)/2 + C2
            u64t num = mul2_(nl, nr);
            u64t den = mul2_(dl, dr);
            float nlo, nhi, dlo, dhi;
            upk2(num, nlo, nhi);
            upk2(den, dlo, dhi);
            // fraction pair-combine: nlo/dlo + nhi/dhi = rr/qq
            rr[o] = fmaf(nlo, dhi, nhi * dlo);
            qq[o] = dlo * dhi;
        }
        // combine the two pairs: one RCP per 4 pixels
        float Rt = fmaf(rr[0], qq[1], rr[1] * qq[0]);
        float Qt = qq[0] * qq[1];
        lsum += __fdividef(Rt, Qt);
    }

    // -------- Block reduce -> atomic; last block finalizes -------------------
#pragma unroll
    for (int off = 16; off; off >>= 1)
        lsum += __shfl_xor_sync(0xffffffffu, lsum, off);
    if ((tid & 31) == 0) red[tid >> 5] = lsum;
    __syncthreads();
    if (tid == 0) {
        float s = 0.f;
#pragma unroll
        for (int i = 0; i < 8; i++) s += red[i];
        atomicAdd(&g_acc, (double)s);
        __threadfence();
        unsigned int total = gridDim.x * gridDim.y * gridDim.z;
        unsigned int old = atomicAdd(&g_cnt, 1u);
        if (old == total - 1u) {
            double tot = atomicAdd(&g_acc, 0.0);
            out[0] = 1.0f - (float)(tot / 25165824.0);   // 32*3*512*512
            g_acc = 0.0;
            __threadfence();
            g_cnt = 0;
        }
    }
}

extern "C" void kernel_launch(void* const* d_in, const int* in_sizes, int n_in,
                              void* d_out, int out_size) {
    const float* A = (const float*)d_in[0];   // denoised
    const float* B = (const float*)d_in[1];   // clean
    float* out = (float*)d_out;

    dim3 grid(512 / TW, 512 / TH, 32 * 3);    // (16, 16, 96)
    ssim_main_k<<<grid, 256>>>(A, B, out);
}

// round 11
// speedup vs baseline: 1.0676x; 1.0676x over previous
#include <cuda_runtime.h>

// SSIM loss, fused single kernel, f32x2-packed separable 11x11 Gaussian conv.
// 4-channel reformulation: s=cx+cy, d=cx-cy; conv (s, d, s^2, d^2).
//   P=mu_s^2, Q=mu_d^2, A=E[s^2], B=E[d^2]:
//   num = ((P-Q)/2+C1) * ((A-B-P+Q)/2+C2)
//   den = ((P+Q)/2+C1) * ((A+B-P-Q)/2+C2)
// 32x32 tile + halo 5, static SMEM, 4-row phase-2 groups split into
// per-(s|d) channel-set items (336 items -> balanced issue wall).
// Epilogue: fraction tree, one MUFU.RCP per 4 px.

#define TW 32
#define TH 32
#define HALO 5
#define KS 11
#define HWD 42
#define SWX 48            // ss/sd row stride (floats)
#define S2  22            // sv2 row stride (u64 elems)

typedef unsigned long long u64t;

__device__ double g_acc = 0.0;
__device__ unsigned int g_cnt = 0;

__device__ constexpr float GW[11] = {
    0.00102838f, 0.00759876f, 0.03600078f, 0.10936069f, 0.21300553f,
    0.26601173f,
    0.21300553f, 0.10936069f, 0.03600078f, 0.00759876f, 0.00102838f};

__device__ __forceinline__ u64t pk2(float lo, float hi) {
    u64t r; asm("mov.b64 %0,{%1,%2};" : "=l"(r) : "f"(lo), "f"(hi)); return r;
}
__device__ __forceinline__ void upk2(u64t v, float& lo, float& hi) {
    asm("mov.b64 {%0,%1},%2;" : "=f"(lo), "=f"(hi) : "l"(v));
}
__device__ __forceinline__ u64t fma2_(u64t a, u64t b, u64t c) {
    u64t d; asm("fma.rn.f32x2 %0,%1,%2,%3;" : "=l"(d) : "l"(a), "l"(b), "l"(c)); return d;
}
__device__ __forceinline__ u64t mul2_(u64t a, u64t b) {
    u64t d; asm("mul.rn.f32x2 %0,%1,%2;" : "=l"(d) : "l"(a), "l"(b)); return d;
}
__device__ __forceinline__ u64t add2_(u64t a, u64t b) {
    u64t d; asm("add.rn.f32x2 %0,%1,%2;" : "=l"(d) : "l"(a), "l"(b)); return d;
}
__device__ __forceinline__ u64t sub2_(u64t a, u64t b) {
    u64t d; asm("sub.rn.f32x2 %0,%1,%2;" : "=l"(d) : "l"(a), "l"(b)); return d;
}

__device__ __forceinline__ constexpr int WS(int j) { return j < 6 ? j : 10 - j; }

__global__ __launch_bounds__(256, 4)
void ssim_main_k(const float* __restrict__ A, const float* __restrict__ Bp,
                 float* __restrict__ out) {
    __shared__ __align__(16) float ss[HWD][SWX];
    __shared__ __align__(16) float sd[HWD][SWX];
    __shared__ __align__(16) u64t  sv2[4][TH][S2];
    __shared__ float red[8];

    const int tid = threadIdx.x;
    const int tx0 = blockIdx.x * TW;
    const int ty0 = blockIdx.y * TH;
    const size_t base = (size_t)blockIdx.z * (512 * 512);

    u64t wq[6];
#pragma unroll
    for (int j = 0; j < 6; j++) wq[j] = pk2(GW[j], GW[j]);

    // -------- Phase 1: halo load (col pairs), clip, s=cx+cy, d=cx-cy --------
    // 882 items = 42 rows x 21 col-pairs; STS.64 per array.
    const bool interior = (blockIdx.x != 0) && (blockIdx.x != 15) &&
                          (blockIdx.y != 0) && (blockIdx.y != 15);
    if (interior) {
#pragma unroll
        for (int i = tid; i < 42 * 21; i += 256) {
            int r = i / 21, c2 = i - r * 21;
            size_t idx = base + (size_t)(ty0 + r - HALO) * 512 + (tx0 + 2 * c2 - HALO);
            float cx0 = __saturatef(__ldg(A + idx));
            float cx1 = __saturatef(__ldg(A + idx + 1));
            float cy0 = __saturatef(__ldg(Bp + idx));
            float cy1 = __saturatef(__ldg(Bp + idx + 1));
            *(float2*)&ss[r][2 * c2] = make_float2(cx0 + cy0, cx1 + cy1);
            *(float2*)&sd[r][2 * c2] = make_float2(cx0 - cy0, cx1 - cy1);
        }
    } else {
#pragma unroll
        for (int i = tid; i < 42 * 21; i += 256) {
            int r = i / 21, c2 = i - r * 21;
            int gy = ty0 + r - HALO;
            int gx = tx0 + 2 * c2 - HALO;
            float cx0 = 0.f, cy0 = 0.f, cx1 = 0.f, cy1 = 0.f;
            bool rowok = (unsigned)gy < 512u;
            if (rowok && (unsigned)gx < 512u) {
                size_t idx = base + (size_t)gy * 512 + gx;
                cx0 = __saturatef(__ldg(A + idx));
                cy0 = __saturatef(__ldg(Bp + idx));
            }
            if (rowok && (unsigned)(gx + 1) < 512u) {
                size_t idx = base + (size_t)gy * 512 + gx + 1;
                cx1 = __saturatef(__ldg(A + idx));
                cy1 = __saturatef(__ldg(Bp + idx));
            }
            *(float2*)&ss[r][2 * c2] = make_float2(cx0 + cy0, cx1 + cy1);
            *(float2*)&sd[r][2 * c2] = make_float2(cx0 - cy0, cx1 - cy1);
        }
    }
    __syncthreads();

    // -------- Phase 2: vertical conv, channel-set split items ----------------
    // 336 items = 2 chsets (s | d) x 8 rowgroups (4 rows) x 21 col-pairs.
    // s-item: channels {mu_s, E[s^2]}; d-item: {mu_d, E[d^2]}. Same total LDS
    // bytes as fused items, half-size instruction streams -> balanced wall.
    for (int i = tid; i < 336; i += 256) {
        const int isD = (i >= 168) ? 1 : 0;
        const int j0 = i - 168 * isD;
        const int g = j0 / 21;
        const int k = j0 - 21 * g;
        const int r0 = g * 4;
        const float* p = isD ? &sd[r0][2 * k] : &ss[r0][2 * k];
        u64t a1[4] = {0, 0, 0, 0}, a2[4] = {0, 0, 0, 0};
#pragma unroll
        for (int p14 = 0; p14 < 14; p14++) {
            float2 vv = *(const float2*)(p + p14 * SWX);
            u64t V = pk2(vv.x, vv.y);
            u64t VV = mul2_(V, V);
#pragma unroll
            for (int o = 0; o < 4; o++) {
                int j = p14 - o;
                if (j >= 0 && j < KS) {
                    u64t w = wq[WS(j)];
                    a1[o] = fma2_(w, V,  a1[o]);
                    a2[o] = fma2_(w, VV, a2[o]);
                }
            }
        }
#pragma unroll
        for (int o = 0; o < 4; o++) {
            int row = r0 + o;
            sv2[isD][row][k]     = a1[o];   // ch0 = mu_s, ch1 = mu_d
            sv2[2 + isD][row][k] = a2[o];   // ch2 = A,    ch3 = B
        }
    }
    __syncthreads();

    // -------- Phase 3: horizontal conv + SSIM, 256 items ---------------------
    // item = 1 row x 4 output cols (2 packed outputs); 32 rows x 8 colgroups
    float lsum = 0.f;
    {
        const int r  = tid >> 3;
        const int cg = tid & 7;
        const int m0 = 2 * cg;           // packed elems m0 .. m0+6
        u64t acc[4][2];
#pragma unroll
        for (int ch = 0; ch < 4; ch++) {
            const u64t* rowp = &sv2[ch][r][m0];
            u64t E[7];
            ulonglong2 q0 = *(const ulonglong2*)(rowp);
            ulonglong2 q1 = *(const ulonglong2*)(rowp + 2);
            ulonglong2 q2 = *(const ulonglong2*)(rowp + 4);
            E[0] = q0.x; E[1] = q0.y; E[2] = q1.x; E[3] = q1.y;
            E[4] = q2.x; E[5] = q2.y; E[6] = rowp[6];
            float flo[7], fhi[7];
#pragma unroll
            for (int t = 0; t < 7; t++) upk2(E[t], flo[t], fhi[t]);
            u64t O[6];
#pragma unroll
            for (int t = 0; t < 6; t++) O[t] = pk2(fhi[t], flo[t + 1]);
#pragma unroll
            for (int o = 0; o < 2; o++) {
                u64t a = mul2_(wq[WS(0)], E[o]);
#pragma unroll
                for (int j = 1; j < KS; j++) {
                    u64t v = (j & 1) ? O[o + (j - 1) / 2] : E[o + j / 2];
                    a = fma2_(wq[WS(j)], v, a);
                }
                acc[ch][o] = a;
            }
        }
        const u64t HALF = pk2(0.5f, 0.5f);
        const u64t C1q = pk2(1e-4f, 1e-4f);
        const u64t C2q = pk2(9e-4f, 9e-4f);
        float rr[2], qq[2];
#pragma unroll
        for (int o = 0; o < 2; o++) {
            u64t mus = acc[0][o], mud = acc[1][o];
            u64t Aq  = acc[2][o], Bq  = acc[3][o];
            u64t P = mul2_(mus, mus);
            u64t Q = mul2_(mud, mud);
            u64t PQd = sub2_(P, Q);
            u64t PQs = add2_(P, Q);
            u64t ABd = sub2_(Aq, Bq);
            u64t ABs = add2_(Aq, Bq);
            u64t nl = fma2_(HALF, PQd, C1q);              // (P-Q)/2 + C1
            u64t nr = fma2_(HALF, sub2_(ABd, PQd), C2q);  // (A-B-P+Q)/2 + C2
            u64t dl = fma2_(HALF, PQs, C1q);              // (P+Q)/2 + C1
            u64t dr = fma2_(HALF, sub2_(ABs, PQs), C2q);  // (A+B-P-Q)/2 + C2
            u64t num = mul2_(nl, nr);
            u64t den = mul2_(dl, dr);
            float nlo, nhi, dlo, dhi;
            upk2(num, nlo, nhi);
            upk2(den, dlo, dhi);
            rr[o] = fmaf(nlo, dhi, nhi * dlo);   // nlo/dlo + nhi/dhi
            qq[o] = dlo * dhi;
        }
        float Rt = fmaf(rr[0], qq[1], rr[1] * qq[0]);
        float Qt = qq[0] * qq[1];
        lsum += __fdividef(Rt, Qt);              // one RCP per 4 px
    }

    // -------- Block reduce -> atomic; last block finalizes -------------------
#pragma unroll
    for (int off = 16; off; off >>= 1)
        lsum += __shfl_xor_sync(0xffffffffu, lsum, off);
    if ((tid & 31) == 0) red[tid >> 5] = lsum;
    __syncthreads();
    if (tid == 0) {
        float s = 0.f;
#pragma unroll
        for (int i = 0; i < 8; i++) s += red[i];
        atomicAdd(&g_acc, (double)s);
        __threadfence();
        unsigned int total = gridDim.x * gridDim.y * gridDim.z;
        unsigned int old = atomicAdd(&g_cnt, 1u);
        if (old == total - 1u) {
            double tot = atomicAdd(&g_acc, 0.0);
            out[0] = 1.0f - (float)(tot / 25165824.0);   // 32*3*512*512
            g_acc = 0.0;
            __threadfence();
            g_cnt = 0;
        }
    }
}

extern "C" void kernel_launch(void* const* d_in, const int* in_sizes, int n_in,
                              void* d_out, int out_size) {
    const float* A = (const float*)d_in[0];   // denoised
    const float* B = (const float*)d_in[1];   // clean
    float* out = (float*)d_out;

    dim3 grid(512 / TW, 512 / TH, 32 * 3);    // (16, 16, 96)
    ssim_main_k<<<grid, 256>>>(A, B, out);
}